// round 15
// baseline (speedup 1.0000x reference)
#include <cuda_runtime.h>
#include <cuda_bf16.h>
#include <cuda_fp16.h>
#include <math.h>
#include <stdint.h>

// Problem constants
#define B_    2
#define T_    2048
#define V_    32000
#define DM    1024
#define DI_   2048
#define NS    16
#define RR    64
#define LL    4
#define KK    4
#define MTOK  (B_*T_)   // 4096

typedef __nv_bfloat16 bf16;

// ---------------- scratch (device globals; no allocation allowed) ----------
__device__ float g_x   [MTOK*DM];        // residual stream (fp32)
__device__ float g_xz  [MTOK*2*DI_];     // in_proj output
__device__ float g_xc  [MTOK*DI_];       // conv+silu output (fp32 for scan)
__device__ float g_proj[MTOK*96];        // x_proj output
__device__ float g_dt  [MTOK*DI_];       // softplus dt
__device__ float g_part[4*MTOK*128];     // split-K partials for x_proj
// 16-bit hi/lo planes for GEMM operands (bf16 or fp16 bits, same storage)
__device__ bf16 g_ah[MTOK*DI_], g_al[MTOK*DI_];     // A planes (max 4096x2048)
__device__ bf16 g_wh[V_*DM],    g_wl[V_*DM];        // W planes (max 32000x1024)

// ---------------- helpers ---------------------------------------------------
__device__ __forceinline__ float softplusf(float x) {
    return x > 20.f ? x : log1pf(expf(x));
}
__device__ __forceinline__ float siluf(float x) {
    return x / (1.f + __expf(-x));
}
__device__ __forceinline__ uint32_t smem_u32(const void* p) {
    uint32_t a;
    asm("{ .reg .u64 t; cvta.to.shared.u64 t, %1; cvt.u32.u64 %0, t; }"
        : "=r"(a) : "l"(p));
    return a;
}
__device__ __forceinline__ void ldsm4(uint32_t* r, uint32_t addr) {
    asm volatile("ldmatrix.sync.aligned.m8n8.x4.shared.b16 {%0,%1,%2,%3}, [%4];"
        : "=r"(r[0]), "=r"(r[1]), "=r"(r[2]), "=r"(r[3]) : "r"(addr));
}
__device__ __forceinline__ void mma_bf(float* d, const uint32_t* a, uint32_t b0, uint32_t b1) {
    asm volatile(
        "mma.sync.aligned.m16n8k16.row.col.f32.bf16.bf16.f32 "
        "{%0,%1,%2,%3}, {%4,%5,%6,%7}, {%8,%9}, {%0,%1,%2,%3};"
        : "+f"(d[0]), "+f"(d[1]), "+f"(d[2]), "+f"(d[3])
        : "r"(a[0]), "r"(a[1]), "r"(a[2]), "r"(a[3]), "r"(b0), "r"(b1));
}
__device__ __forceinline__ void mma_fp16(float* d, const uint32_t* a, uint32_t b0, uint32_t b1) {
    asm volatile(
        "mma.sync.aligned.m16n8k16.row.col.f32.f16.f16.f32 "
        "{%0,%1,%2,%3}, {%4,%5,%6,%7}, {%8,%9}, {%0,%1,%2,%3};"
        : "+f"(d[0]), "+f"(d[1]), "+f"(d[2]), "+f"(d[3])
        : "r"(a[0]), "r"(a[1]), "r"(a[2]), "r"(a[3]), "r"(b0), "r"(b1));
}
__device__ __forceinline__ void cpasync16(uint32_t dst, const void* src) {
    asm volatile("cp.async.cg.shared.global [%0], [%1], 16;" :: "r"(dst), "l"(src));
}
#define CP_COMMIT() asm volatile("cp.async.commit_group;" ::: "memory")
#define CP_WAIT(n)  asm volatile("cp.async.wait_group %0;" :: "n"(n) : "memory")

// packed f32x2 helpers (sm_100+ baseline PTX)
typedef unsigned long long u64;
__device__ __forceinline__ u64 pack2(float x, float y) {
    u64 r; asm("mov.b64 %0, {%1, %2};" : "=l"(r) : "f"(x), "f"(y)); return r;
}
__device__ __forceinline__ void unpack2(u64 v, float& x, float& y) {
    asm("mov.b64 {%0, %1}, %2;" : "=f"(x), "=f"(y) : "l"(v));
}
__device__ __forceinline__ u64 mul2_(u64 a, u64 b) {
    u64 r; asm("mul.rn.f32x2 %0, %1, %2;" : "=l"(r) : "l"(a), "l"(b)); return r;
}
__device__ __forceinline__ u64 fma2_(u64 a, u64 b, u64 c) {
    u64 r; asm("fma.rn.f32x2 %0, %1, %2, %3;" : "=l"(r) : "l"(a), "l"(b), "l"(c)); return r;
}

// hi/lo bf16 split of 4 floats, packed as 2x uint2 (memory order preserved)
__device__ __forceinline__ void split4(float4 v, uint2& hi, uint2& lo) {
    float f[4] = {v.x, v.y, v.z, v.w};
    uint32_t h[4], l[4];
    #pragma unroll
    for (int i = 0; i < 4; ++i) {
        bf16 hb = __float2bfloat16_rn(f[i]);
        float rem = f[i] - __bfloat162float(hb);
        bf16 lb = __float2bfloat16_rn(rem);
        h[i] = (uint32_t)__bfloat16_as_ushort(hb);
        l[i] = (uint32_t)__bfloat16_as_ushort(lb);
    }
    hi.x = h[0] | (h[1] << 16); hi.y = h[2] | (h[3] << 16);
    lo.x = l[0] | (l[1] << 16); lo.y = l[2] | (l[3] << 16);
}
// hi/lo fp16 split of 4 floats
__device__ __forceinline__ void split4h(float4 v, uint2& hi, uint2& lo) {
    float f[4] = {v.x, v.y, v.z, v.w};
    uint32_t h[4], l[4];
    #pragma unroll
    for (int i = 0; i < 4; ++i) {
        __half hb = __float2half_rn(f[i]);
        float rem = f[i] - __half2float(hb);
        __half lb = __float2half_rn(rem);
        h[i] = (uint32_t)__half_as_ushort(hb);
        l[i] = (uint32_t)__half_as_ushort(lb);
    }
    hi.x = h[0] | (h[1] << 16); hi.y = h[2] | (h[3] << 16);
    lo.x = l[0] | (l[1] << 16); lo.y = l[2] | (l[3] << 16);
}
__device__ __forceinline__ void split1(float v, bf16& h, bf16& l) {
    h = __float2bfloat16_rn(v);
    l = __float2bfloat16_rn(v - __bfloat162float(h));
}
__device__ __forceinline__ void split1h(float v, unsigned short& h, unsigned short& l) {
    __half hb = __float2half_rn(v);
    __half lb = __float2half_rn(v - __half2float(hb));
    h = __half_as_ushort(hb);
    l = __half_as_ushort(lb);
}

// ---------------- weight split: fp32 (Nvalid x K) -> bf16 planes ------------
__global__ void wsplit_kernel(const float* __restrict__ src,
                              bf16* __restrict__ hi, bf16* __restrict__ lo,
                              int Nvalid, int K, long total) {
    long i = ((long)blockIdx.x * blockDim.x + threadIdx.x) * 4;
    if (i >= total) return;
    int row = (int)(i / K);
    uint2 h, l;
    if (row < Nvalid) {
        float4 v = *(const float4*)(src + i);
        split4(v, h, l);
    } else {
        h.x = h.y = l.x = l.y = 0u;
    }
    *(uint2*)(hi + i) = h;
    *(uint2*)(lo + i) = l;
}

// ---------------- weight round: fp32 -> single fp16 plane -------------------
__global__ void wsplit_f16_kernel(const float* __restrict__ src,
                                  __half* __restrict__ hi, long total) {
    long i = ((long)blockIdx.x * blockDim.x + threadIdx.x) * 4;
    if (i >= total) return;
    float4 v = *(const float4*)(src + i);
    uint32_t h0 = (uint32_t)__half_as_ushort(__float2half_rn(v.x));
    uint32_t h1 = (uint32_t)__half_as_ushort(__float2half_rn(v.y));
    uint32_t h2 = (uint32_t)__half_as_ushort(__float2half_rn(v.z));
    uint32_t h3 = (uint32_t)__half_as_ushort(__float2half_rn(v.w));
    uint2 h; h.x = h0 | (h1 << 16); h.y = h2 | (h3 << 16);
    *(uint2*)(hi + i) = h;
}

// ---------------- x_proj split-K reduce + fused dt_r bf16 split -------------
__global__ void xp_reduce_kernel(const float* __restrict__ part,
                                 float* __restrict__ proj,
                                 bf16* __restrict__ dth, bf16* __restrict__ dtl) {
    int t = blockIdx.x * blockDim.x + threadIdx.x;   // over 4096*24
    if (t >= MTOK * 24) return;
    int row = t / 24, c4 = (t % 24) * 4;
    float4 s = *(const float4*)(part + (size_t)row * 128 + c4);
    #pragma unroll
    for (int z = 1; z < 4; ++z) {
        float4 p = *(const float4*)(part + ((size_t)z * MTOK + row) * 128 + c4);
        s.x += p.x; s.y += p.y; s.z += p.z; s.w += p.w;
    }
    *(float4*)(proj + (size_t)row * 96 + c4) = s;
    if (c4 < 64) {
        uint2 h, l;
        split4(s, h, l);
        *(uint2*)(dth + (size_t)row * 64 + c4) = h;
        *(uint2*)(dtl + (size_t)row * 64 + c4) = l;
    }
}

// ---------------- HMMA GEMM on 16-bit planes --------------------------------
// MODE 0: bf16, 3 passes, NT=4, K32, 2-stage (two barriers/chunk).
// MODE 1: fp16 2-pass, NT=3, K32, 3-stage single-barrier pipeline.
// MODE 2: fp16 1-pass, NT=2, K64, 3-stage single-barrier pipeline.
// Block tile 128x128, 2 CTAs/SM. K32 pitch 40 (80B), K64 pitch 72 (144B).
template<int ACT, bool BIAS, bool ACC, int MODE, bool K64>
__global__ __launch_bounds__(256, 2) void gemm_bf(
    int M, int N, int K,
    const bf16* __restrict__ Ah, const bf16* __restrict__ Al, int lda,
    const bf16* __restrict__ Wh, const bf16* __restrict__ Wl, int ldw,
    float* __restrict__ C, int ldc,
    const float* __restrict__ bias)
{
    constexpr int NT = (MODE == 0) ? 4 : ((MODE == 1) ? 3 : 2);
    constexpr int WT = (MODE == 2) ? 1 : 2;
    constexpr bool PIPE3 = (MODE != 0);
    constexpr int STAGES = PIPE3 ? 3 : 2;
    constexpr int PE = K64 ? 72 : 40;
    constexpr int PB = PE * 2;
    constexpr uint32_t TB = 128u * PB;
    constexpr uint32_t STAGE = NT * TB;
    constexpr int KSTEPS = K64 ? 4 : 2;
    extern __shared__ char sm[];
    int tid = threadIdx.x;
    int lane = tid & 31, wid = tid >> 5;
    int warp_m = wid >> 2, warp_n = wid & 3;
    int bm = blockIdx.x * 128, bn = blockIdx.y * 128;
    int kbase = blockIdx.z * K;
    int NC = K >> (K64 ? 6 : 5);
    uint32_t smb = smem_u32(sm);

    int a_row = warp_m * 64 + (lane & 15);
    int a_col = (lane >> 4) * 8;
    int b_row = warp_n * 32 + (lane & 7) + ((lane >> 4) << 3);
    int b_col = ((lane >> 3) & 1) * 8;

    float acc[4][4][4];
    #pragma unroll
    for (int i = 0; i < 4; ++i)
        #pragma unroll
        for (int j = 0; j < 4; ++j)
            #pragma unroll
            for (int q = 0; q < 4; ++q) acc[i][j][q] = 0.f;

    int c_row = K64 ? (tid >> 3) : (tid >> 2);
    int c_seg = K64 ? (tid & 7)  : (tid & 3);
    constexpr int LD_ITERS = K64 ? 4 : 2;
    constexpr int LD_ROWS  = K64 ? 32 : 64;
    uint32_t c_doff = (uint32_t)(c_row * PB + c_seg * 16);

    auto issue = [&](int c, int s) {
        int k0 = kbase + (c << (K64 ? 6 : 5));
        uint32_t sb = smb + (uint32_t)s * STAGE;
        #pragma unroll
        for (int it = 0; it < LD_ITERS; ++it) {
            int row = c_row + it * LD_ROWS;
            uint32_t doff = c_doff + (uint32_t)(it * LD_ROWS * PB);
            size_t aofs = (size_t)(bm + row) * lda + k0 + c_seg * 8;
            size_t wofs = (size_t)(bn + row) * ldw + k0 + c_seg * 8;
            cpasync16(sb + 0*TB + doff, Ah + aofs);
            if (MODE != 2) cpasync16(sb + 1*TB + doff, Al + aofs);
            cpasync16(sb + WT*TB + doff, Wh + wofs);
            if (MODE == 0) cpasync16(sb + 3*TB + doff, Wl + wofs);
        }
        CP_COMMIT();
    };

    int committed = (NC < 2) ? NC : 2;
    for (int c = 0; c < committed; ++c) issue(c, c % STAGES);

    for (int c = 0; c < NC; ++c) {
        if (committed > c + 1) CP_WAIT(1);
        else                   CP_WAIT(0);
        __syncthreads();
        if (PIPE3) {
            // stage (committed%3) == (c+2)%3 == (c-1)%3 was freed by the barrier
            if (committed < NC) { issue(committed, committed % 3); ++committed; }
        }

        uint32_t sb = smb + (uint32_t)(c % STAGES) * STAGE;
        #pragma unroll
        for (int ks = 0; ks < KSTEPS; ++ks) {
            uint32_t af[4][4], bh[2][4];
            #pragma unroll
            for (int i = 0; i < 4; ++i)
                ldsm4(af[i], sb + 0*TB + 2u*(uint32_t)((a_row + i*16)*PE + a_col + ks*16));
            #pragma unroll
            for (int j = 0; j < 2; ++j)
                ldsm4(bh[j], sb + WT*TB + 2u*(uint32_t)((b_row + j*16)*PE + b_col + ks*16));
            #pragma unroll
            for (int i = 0; i < 4; ++i)
                #pragma unroll
                for (int jt = 0; jt < 4; ++jt) {
                    if (MODE == 0) mma_bf  (acc[i][jt], af[i], bh[jt>>1][(jt&1)*2], bh[jt>>1][(jt&1)*2+1]);
                    else           mma_fp16(acc[i][jt], af[i], bh[jt>>1][(jt&1)*2], bh[jt>>1][(jt&1)*2+1]);
                }
            if (MODE == 0) {
                uint32_t bl[2][4];
                #pragma unroll
                for (int j = 0; j < 2; ++j)
                    ldsm4(bl[j], sb + 3*TB + 2u*(uint32_t)((b_row + j*16)*PE + b_col + ks*16));
                #pragma unroll
                for (int i = 0; i < 4; ++i)
                    #pragma unroll
                    for (int jt = 0; jt < 4; ++jt)
                        mma_bf(acc[i][jt], af[i], bl[jt>>1][(jt&1)*2], bl[jt>>1][(jt&1)*2+1]);
            }
            if (MODE != 2) {
                #pragma unroll
                for (int i = 0; i < 4; ++i)
                    ldsm4(af[i], sb + 1*TB + 2u*(uint32_t)((a_row + i*16)*PE + a_col + ks*16));
                #pragma unroll
                for (int i = 0; i < 4; ++i)
                    #pragma unroll
                    for (int jt = 0; jt < 4; ++jt) {
                        if (MODE == 0) mma_bf  (acc[i][jt], af[i], bh[jt>>1][(jt&1)*2], bh[jt>>1][(jt&1)*2+1]);
                        else           mma_fp16(acc[i][jt], af[i], bh[jt>>1][(jt&1)*2], bh[jt>>1][(jt&1)*2+1]);
                    }
            }
        }
        if (!PIPE3) {
            __syncthreads();
            if (committed < NC) { issue(committed, committed & 1); ++committed; }
        }
    }

    // epilogue
    float* Cz = C + (size_t)blockIdx.z * M * ldc;
    #pragma unroll
    for (int i = 0; i < 4; ++i) {
        int r0 = bm + warp_m * 64 + i * 16 + (lane >> 2);
        #pragma unroll
        for (int jt = 0; jt < 4; ++jt) {
            int col = bn + warp_n * 32 + jt * 8 + (lane & 3) * 2;
            #pragma unroll
            for (int half = 0; half < 2; ++half) {
                int r = r0 + half * 8;
                float vx = acc[i][jt][half * 2 + 0];
                float vy = acc[i][jt][half * 2 + 1];
                if (BIAS) { vx += bias[col]; vy += bias[col + 1]; }
                float* cp = Cz + (size_t)r * ldc + col;
                if (ACC) {
                    float2 cc = *(float2*)cp;
                    vx += cc.x; vy += cc.y;
                }
                if (ACT == 1) { vx = softplusf(vx); vy = softplusf(vy); }
                float2 o; o.x = vx; o.y = vy;
                *(float2*)cp = o;
            }
        }
    }
}

#define GSMEM_BF    (2*4*10240)   // 81920  (MODE0, K32, 2-stage)
#define GSMEM_F16P2 (3*3*10240)   // 92160  (MODE1, K32, 3-stage)
#define GSMEM_F16   (3*2*18432)   // 110592 (MODE2, K64, 3-stage)

// ---------------- embed -----------------------------------------------------
__global__ void embed_kernel(const int* __restrict__ ids,
                             const float* __restrict__ E,
                             float* __restrict__ x) {
    int i = blockIdx.x * blockDim.x + threadIdx.x;
    if (i >= MTOK * DM) return;
    int row = i >> 10;
    int d   = i & (DM - 1);
    x[i] = E[(size_t)ids[row] * DM + d];
}

// ---------------- layernorm -> 16-bit planes --------------------------------
// OUTMODE 0: bf16 hi/lo pair. 1: fp16 hi/lo pair. 2: fp16 single plane.
template<int OUTMODE>
__global__ __launch_bounds__(256) void ln_planes_kernel(
    const float* __restrict__ x,
    const float* __restrict__ w,
    const float* __restrict__ b,
    bf16* __restrict__ hi, bf16* __restrict__ lo)
{
    int row = blockIdx.x;
    int tid = threadIdx.x;
    const float4* xr = (const float4*)(x + (size_t)row * DM);
    float4 v = xr[tid];
    float s  = v.x + v.y + v.z + v.w;
    float sq = v.x*v.x + v.y*v.y + v.z*v.z + v.w*v.w;
    #pragma unroll
    for (int o = 16; o > 0; o >>= 1) {
        s  += __shfl_xor_sync(0xffffffff, s,  o);
        sq += __shfl_xor_sync(0xffffffff, sq, o);
    }
    __shared__ float rs[8], rq[8];
    int warp = tid >> 5, lane = tid & 31;
    if (lane == 0) { rs[warp] = s; rq[warp] = sq; }
    __syncthreads();
    __shared__ float smu, srstd;
    if (tid == 0) {
        float ts = 0.f, tq = 0.f;
        #pragma unroll
        for (int i = 0; i < 8; ++i) { ts += rs[i]; tq += rq[i]; }
        float mu  = ts * (1.f / DM);
        float var = tq * (1.f / DM) - mu * mu;
        smu = mu;
        srstd = rsqrtf(var + 1e-5f);
    }
    __syncthreads();
    float mu = smu, rstd = srstd;
    float4 wv = ((const float4*)w)[tid];
    float4 bv = ((const float4*)b)[tid];
    float4 o;
    o.x = (v.x - mu) * rstd * wv.x + bv.x;
    o.y = (v.y - mu) * rstd * wv.y + bv.y;
    o.z = (v.z - mu) * rstd * wv.z + bv.z;
    o.w = (v.w - mu) * rstd * wv.w + bv.w;
    if (OUTMODE == 2) {
        uint32_t h0 = (uint32_t)__half_as_ushort(__float2half_rn(o.x));
        uint32_t h1 = (uint32_t)__half_as_ushort(__float2half_rn(o.y));
        uint32_t h2 = (uint32_t)__half_as_ushort(__float2half_rn(o.z));
        uint32_t h3 = (uint32_t)__half_as_ushort(__float2half_rn(o.w));
        uint2 h; h.x = h0 | (h1 << 16); h.y = h2 | (h3 << 16);
        *(uint2*)(hi + (size_t)row * DM + tid * 4) = h;
    } else {
        uint2 h, l;
        if (OUTMODE == 1) split4h(o, h, l); else split4(o, h, l);
        *(uint2*)(hi + (size_t)row * DM + tid * 4) = h;
        *(uint2*)(lo + (size_t)row * DM + tid * 4) = l;
    }
}

// ---------------- causal dwconv (K=4) + silu -> fp32 + bf16 planes ----------
__global__ void conv_silu_kernel(const float* __restrict__ xz,
                                 const float* __restrict__ cw,
                                 const float* __restrict__ cb,
                                 float* __restrict__ xc,
                                 bf16* __restrict__ hi, bf16* __restrict__ lo) {
    int i = blockIdx.x * blockDim.x + threadIdx.x;
    if (i >= MTOK * DI_) return;
    int c  = i & (DI_ - 1);
    int bt = i >> 11;
    int t  = bt & (T_ - 1);
    float acc = cb[c];
    #pragma unroll
    for (int k = 0; k < KK; ++k) {
        int tt = t + k - (KK - 1);
        if (tt >= 0)
            acc += xz[(size_t)(bt + k - (KK - 1)) * (2*DI_) + c] * cw[c*KK + k];
    }
    float v = siluf(acc);
    xc[i] = v;
    bf16 h, l;
    split1(v, h, l);
    hi[i] = h; lo[i] = l;
}

// ---------------- selective scan with smem-staged operands, f32x2 state -----
#define CH 128
#define TT 32
#define SC_STAGEF (3*TT*CH + TT*32)      // floats per stage: 13312
#define SC_SMEM   (2*SC_STAGEF*4)        // bytes: 106496

__global__ __launch_bounds__(CH) void scan_kernel(
    const float* __restrict__ xc,
    const float* __restrict__ dtb,
    const float* __restrict__ proj,
    const float* __restrict__ xz,
    const float* __restrict__ Alog,
    const float* __restrict__ Dp,
    unsigned short* __restrict__ yh, unsigned short* __restrict__ yl)
{
    extern __shared__ float ss[];
    int tid = threadIdx.x;
    int d0  = blockIdx.x * CH;
    int b   = blockIdx.y;
    int d   = d0 + tid;

    uint32_t sbase = smem_u32(ss);

    auto issue_tile = [&](int k, int s) {
        uint32_t sb = sbase + (uint32_t)(s * SC_STAGEF * 4);
        int t0 = k * TT;
        #pragma unroll
        for (int it = 0; it < 8; ++it) {
            int j = it * CH + tid;
            int t = j >> 5;
            int off = (j & 31) * 4;
            size_t g = (size_t)(b * T_ + t0 + t);
            cpasync16(sb + 0*TT*CH*4 + j*16, xc  + g * DI_ + d0 + off);
            cpasync16(sb + 1*TT*CH*4 + j*16, dtb + g * DI_ + d0 + off);
            cpasync16(sb + 2*TT*CH*4 + j*16, xz  + g * (2*DI_) + DI_ + d0 + off);
        }
        #pragma unroll
        for (int it = 0; it < 2; ++it) {
            int j = it * CH + tid;
            int t = j >> 3;
            int c4 = (j & 7) * 4;
            size_t g = (size_t)(b * T_ + t0 + t);
            cpasync16(sb + 3*TT*CH*4 + j*16, proj + g * 96 + RR + c4);
        }
        CP_COMMIT();
    };

    float A[NS];
    bool fast = true;
    #pragma unroll
    for (int n = 0; n < NS; ++n) {
        A[n] = -expf(Alog[(size_t)d * NS + n]);
        fast = fast && (fabsf(A[n] + (float)(n + 1)) <= 1e-3f * (n + 1));
    }
    float Dv = Dp[d];
    u64 h2[8];
    #pragma unroll
    for (int j = 0; j < 8; ++j) h2[j] = 0ull;

    const int ntiles = T_ / TT;    // 64
    issue_tile(0, 0);

    for (int k = 0; k < ntiles; ++k) {
        if (k + 1 < ntiles) { issue_tile(k + 1, (k + 1) & 1); CP_WAIT(1); }
        else                { CP_WAIT(0); }
        __syncthreads();

        float* base = ss + (k & 1) * SC_STAGEF;
        float* s_u  = base;
        float* s_dt = base + 1*TT*CH;
        float* s_z  = base + 2*TT*CH;
        float* s_bc = base + 3*TT*CH;

        for (int i = 0; i < TT; ++i) {
            float u   = s_u [i*CH + tid];
            float dtv = s_dt[i*CH + tid];
            float z   = s_z [i*CH + tid];
            float du  = dtv * u;
            float accv;
            if (fast) {
                float p = __expf(-dtv);
                float q = p * p;
                u64 qq  = pack2(q, q);
                u64 dA2 = pack2(p, q);
                u64 du2 = pack2(du, du);
                u64 acc2 = 0ull;
                #pragma unroll
                for (int j = 0; j < 8; ++j) {
                    u64 B2 = *(const u64*)(s_bc + i*32 + 2*j);
                    u64 C2 = *(const u64*)(s_bc + i*32 + 16 + 2*j);
                    h2[j] = fma2_(dA2, h2[j], mul2_(du2, B2));
                    acc2  = fma2_(h2[j], C2, acc2);
                    if (j < 7) dA2 = mul2_(dA2, qq);
                }
                float a0, a1;
                unpack2(acc2, a0, a1);
                accv = a0 + a1;
            } else {
                accv = 0.f;
                #pragma unroll
                for (int j = 0; j < 8; ++j) {
                    float hx, hy;
                    unpack2(h2[j], hx, hy);
                    float dA0 = __expf(dtv * A[2*j]);
                    float dA1 = __expf(dtv * A[2*j+1]);
                    hx = dA0 * hx + du * s_bc[i*32 + 2*j];
                    hy = dA1 * hy + du * s_bc[i*32 + 2*j + 1];
                    accv += hx * s_bc[i*32 + 16 + 2*j];
                    accv += hy * s_bc[i*32 + 16 + 2*j + 1];
                    h2[j] = pack2(hx, hy);
                }
            }
            float val = (accv + u * Dv) * siluf(z);
            unsigned short vh, vl;
            split1h(val, vh, vl);
            size_t idx = (size_t)(b * T_ + k * TT + i) * DI_ + d;
            yh[idx] = vh;
            yl[idx] = vl;
        }
        __syncthreads();
    }
}

// ---------------- launch ----------------------------------------------------
extern "C" void kernel_launch(void* const* d_in, const int* in_sizes, int n_in,
                              void* d_out, int out_size) {
    const int*   ids       = (const int*)  d_in[0];
    const float* embed_W   = (const float*)d_in[1];
    const float* out_b     = (const float*)d_in[2];
    const float* ln_w      = (const float*)d_in[3];
    const float* ln_b      = (const float*)d_in[4];
    const float* norm_w    = (const float*)d_in[5];
    const float* norm_b    = (const float*)d_in[6];
    const float* in_proj_W = (const float*)d_in[7];
    const float* conv_W    = (const float*)d_in[8];
    const float* conv_b    = (const float*)d_in[9];
    const float* x_proj_W  = (const float*)d_in[10];
    const float* dt_proj_W = (const float*)d_in[11];
    const float* dt_proj_b = (const float*)d_in[12];
    const float* A_log     = (const float*)d_in[13];
    const float* D_param   = (const float*)d_in[14];
    const float* out_projW = (const float*)d_in[15];
    float* out = (float*)d_out;

    float *px, *pxz, *pxc, *pproj, *pdt, *ppart;
    bf16 *pah, *pal, *pwh, *pwl;
    cudaGetSymbolAddress((void**)&px,    g_x);
    cudaGetSymbolAddress((void**)&pxz,   g_xz);
    cudaGetSymbolAddress((void**)&pxc,   g_xc);
    cudaGetSymbolAddress((void**)&pproj, g_proj);
    cudaGetSymbolAddress((void**)&pdt,   g_dt);
    cudaGetSymbolAddress((void**)&ppart, g_part);
    cudaGetSymbolAddress((void**)&pah,   g_ah);
    cudaGetSymbolAddress((void**)&pal,   g_al);
    cudaGetSymbolAddress((void**)&pwh,   g_wh);
    cudaGetSymbolAddress((void**)&pwl,   g_wl);

    cudaFuncSetAttribute(gemm_bf<0,false,false,0,false>,
                         cudaFuncAttributeMaxDynamicSharedMemorySize, GSMEM_BF);
    cudaFuncSetAttribute(gemm_bf<1,true,false,0,false>,
                         cudaFuncAttributeMaxDynamicSharedMemorySize, GSMEM_BF);
    cudaFuncSetAttribute(gemm_bf<0,false,false,1,false>,
                         cudaFuncAttributeMaxDynamicSharedMemorySize, GSMEM_F16P2);
    cudaFuncSetAttribute(gemm_bf<0,false,true,1,false>,
                         cudaFuncAttributeMaxDynamicSharedMemorySize, GSMEM_F16P2);
    cudaFuncSetAttribute(gemm_bf<0,true,false,2,true>,
                         cudaFuncAttributeMaxDynamicSharedMemorySize, GSMEM_F16);
    cudaFuncSetAttribute(scan_kernel,
                         cudaFuncAttributeMaxDynamicSharedMemorySize, SC_SMEM);

    embed_kernel<<<(MTOK*DM + 255)/256, 256>>>(ids, embed_W, px);

    for (int l = 0; l < LL; ++l) {
        // h planes (fp16 hi/lo for MODE-1 in_proj)
        ln_planes_kernel<1><<<MTOK, 256>>>(px, norm_w + l*DM, norm_b + l*DM, pah, pal);

        // in_proj weights -> single fp16 plane, GEMM (fp16 2-pass, K32, 3-stage)
        {
            long tot = (long)2*DI_*DM;
            wsplit_f16_kernel<<<(int)((tot/4 + 255)/256), 256>>>(
                in_proj_W + (size_t)l*tot, (__half*)pwh, tot);
            gemm_bf<0,false,false,1,false><<<dim3(32, 32), 256, GSMEM_F16P2>>>(
                MTOK, 2*DI_, DM, pah, pal, DM, pwh, nullptr, DM, pxz, 2*DI_, nullptr);
        }

        // conv+silu -> xc fp32 + bf16 planes (reuse pah/pal)
        conv_silu_kernel<<<(MTOK*DI_ + 255)/256, 256>>>(
            pxz, conv_W + (size_t)l*DI_*KK, conv_b + (size_t)l*DI_, pxc, pah, pal);

        // x_proj weights (pad 96->128) bf16 planes, split-K GEMM
        {
            long tot = (long)128*DI_;
            wsplit_kernel<<<(int)((tot/4 + 255)/256), 256>>>(
                x_proj_W + (size_t)l*96*DI_, pwh, pwl, 96, DI_, tot);
            gemm_bf<0,false,false,0,false><<<dim3(32, 1, 4), 256, GSMEM_BF>>>(
                MTOK, 128, 512, pah, pal, DI_, pwh, pwl, DI_, ppart, 128, nullptr);
        }

        // dt_proj weights, fused reduce/dtr, GEMM+softplus
        {
            long tot = (long)DI_*RR;
            wsplit_kernel<<<(int)((tot/4 + 255)/256), 256>>>(
                dt_proj_W + (size_t)l*tot, pwh, pwl, DI_, RR, tot);
            xp_reduce_kernel<<<(MTOK*24 + 255)/256, 256>>>(ppart, pproj, pah, pal);
            gemm_bf<1,true,false,0,false><<<dim3(32, 16), 256, GSMEM_BF>>>(
                MTOK, DI_, RR, pah, pal, RR, pwh, pwl, RR, pdt, DI_,
                dt_proj_b + (size_t)l*DI_);
        }

        // scan -> y fp16 hi/lo planes (reuse pah/pal)
        scan_kernel<<<dim3(DI_/CH, B_), CH, SC_SMEM>>>(
            pxc, pdt, pproj, pxz,
            A_log + (size_t)l*DI_*NS, D_param + (size_t)l*DI_,
            (unsigned short*)pah, (unsigned short*)pal);

        // out_proj weights -> single fp16 plane, GEMM (fp16 2-pass, K32, 3-stage, +residual)
        {
            long tot = (long)DM*DI_;
            wsplit_f16_kernel<<<(int)((tot/4 + 255)/256), 256>>>(
                out_projW + (size_t)l*tot, (__half*)pwh, tot);
            gemm_bf<0,false,true,1,false><<<dim3(32, 8), 256, GSMEM_F16P2>>>(
                MTOK, DM, DI_, pah, pal, DI_, pwh, nullptr, DI_, px, DM, nullptr);
        }
    }

    // final LN -> single fp16 plane
    ln_planes_kernel<2><<<MTOK, 256>>>(px, ln_w, ln_b, pah, pal);

    // embed weights -> single fp16 plane, logits GEMM (1-pass fp16, K64, 3-stage)
    {
        long tot = (long)V_*DM;
        wsplit_f16_kernel<<<(int)((tot/4 + 255)/256), 256>>>(
            embed_W, (__half*)pwh, tot);
        gemm_bf<0,true,false,2,true><<<dim3(32, V_/128), 256, GSMEM_F16>>>(
            MTOK, V_, DM, pah, nullptr, DM, pwh, nullptr, DM, out, V_, out_b);
    }
}

// round 16
// speedup vs baseline: 1.0603x; 1.0603x over previous
#include <cuda_runtime.h>
#include <cuda_bf16.h>
#include <cuda_fp16.h>
#include <math.h>
#include <stdint.h>

// Problem constants
#define B_    2
#define T_    2048
#define V_    32000
#define DM    1024
#define DI_   2048
#define NS    16
#define RR    64
#define LL    4
#define KK    4
#define MTOK  (B_*T_)   // 4096

typedef __nv_bfloat16 bf16;

// ---------------- scratch (device globals; no allocation allowed) ----------
__device__ float g_x   [MTOK*DM];        // residual stream (fp32)
__device__ float g_xz  [MTOK*2*DI_];     // in_proj output
__device__ float g_xc  [MTOK*DI_];       // conv+silu output (fp32 for scan)
__device__ float g_proj[MTOK*96];        // x_proj output
__device__ float g_dt  [MTOK*DI_];       // softplus dt
__device__ float g_part[4*MTOK*128];     // split-K partials for x_proj
// 16-bit hi/lo planes for GEMM operands (bf16 or fp16 bits, same storage)
__device__ bf16 g_ah[MTOK*DI_], g_al[MTOK*DI_];     // A planes (max 4096x2048)
__device__ bf16 g_wh[V_*DM],    g_wl[V_*DM];        // W planes (max 32000x1024)

// ---------------- helpers ---------------------------------------------------
__device__ __forceinline__ float softplusf(float x) {
    return x > 20.f ? x : log1pf(expf(x));
}
__device__ __forceinline__ float siluf(float x) {
    return x / (1.f + __expf(-x));
}
__device__ __forceinline__ uint32_t smem_u32(const void* p) {
    uint32_t a;
    asm("{ .reg .u64 t; cvta.to.shared.u64 t, %1; cvt.u32.u64 %0, t; }"
        : "=r"(a) : "l"(p));
    return a;
}
__device__ __forceinline__ void ldsm4(uint32_t* r, uint32_t addr) {
    asm volatile("ldmatrix.sync.aligned.m8n8.x4.shared.b16 {%0,%1,%2,%3}, [%4];"
        : "=r"(r[0]), "=r"(r[1]), "=r"(r[2]), "=r"(r[3]) : "r"(addr));
}
__device__ __forceinline__ void mma_bf(float* d, const uint32_t* a, uint32_t b0, uint32_t b1) {
    asm volatile(
        "mma.sync.aligned.m16n8k16.row.col.f32.bf16.bf16.f32 "
        "{%0,%1,%2,%3}, {%4,%5,%6,%7}, {%8,%9}, {%0,%1,%2,%3};"
        : "+f"(d[0]), "+f"(d[1]), "+f"(d[2]), "+f"(d[3])
        : "r"(a[0]), "r"(a[1]), "r"(a[2]), "r"(a[3]), "r"(b0), "r"(b1));
}
__device__ __forceinline__ void mma_fp16(float* d, const uint32_t* a, uint32_t b0, uint32_t b1) {
    asm volatile(
        "mma.sync.aligned.m16n8k16.row.col.f32.f16.f16.f32 "
        "{%0,%1,%2,%3}, {%4,%5,%6,%7}, {%8,%9}, {%0,%1,%2,%3};"
        : "+f"(d[0]), "+f"(d[1]), "+f"(d[2]), "+f"(d[3])
        : "r"(a[0]), "r"(a[1]), "r"(a[2]), "r"(a[3]), "r"(b0), "r"(b1));
}
__device__ __forceinline__ void cpasync16(uint32_t dst, const void* src) {
    asm volatile("cp.async.cg.shared.global [%0], [%1], 16;" :: "r"(dst), "l"(src));
}
#define CP_COMMIT() asm volatile("cp.async.commit_group;" ::: "memory")
#define CP_WAIT(n)  asm volatile("cp.async.wait_group %0;" :: "n"(n) : "memory")

// packed f32x2 helpers (sm_100+ baseline PTX)
typedef unsigned long long u64;
__device__ __forceinline__ u64 pack2(float x, float y) {
    u64 r; asm("mov.b64 %0, {%1, %2};" : "=l"(r) : "f"(x), "f"(y)); return r;
}
__device__ __forceinline__ void unpack2(u64 v, float& x, float& y) {
    asm("mov.b64 {%0, %1}, %2;" : "=f"(x), "=f"(y) : "l"(v));
}
__device__ __forceinline__ u64 mul2_(u64 a, u64 b) {
    u64 r; asm("mul.rn.f32x2 %0, %1, %2;" : "=l"(r) : "l"(a), "l"(b)); return r;
}
__device__ __forceinline__ u64 fma2_(u64 a, u64 b, u64 c) {
    u64 r; asm("fma.rn.f32x2 %0, %1, %2, %3;" : "=l"(r) : "l"(a), "l"(b), "l"(c)); return r;
}

// hi/lo bf16 split of 4 floats, packed as 2x uint2 (memory order preserved)
__device__ __forceinline__ void split4(float4 v, uint2& hi, uint2& lo) {
    float f[4] = {v.x, v.y, v.z, v.w};
    uint32_t h[4], l[4];
    #pragma unroll
    for (int i = 0; i < 4; ++i) {
        bf16 hb = __float2bfloat16_rn(f[i]);
        float rem = f[i] - __bfloat162float(hb);
        bf16 lb = __float2bfloat16_rn(rem);
        h[i] = (uint32_t)__bfloat16_as_ushort(hb);
        l[i] = (uint32_t)__bfloat16_as_ushort(lb);
    }
    hi.x = h[0] | (h[1] << 16); hi.y = h[2] | (h[3] << 16);
    lo.x = l[0] | (l[1] << 16); lo.y = l[2] | (l[3] << 16);
}
// hi/lo fp16 split of 4 floats
__device__ __forceinline__ void split4h(float4 v, uint2& hi, uint2& lo) {
    float f[4] = {v.x, v.y, v.z, v.w};
    uint32_t h[4], l[4];
    #pragma unroll
    for (int i = 0; i < 4; ++i) {
        __half hb = __float2half_rn(f[i]);
        float rem = f[i] - __half2float(hb);
        __half lb = __float2half_rn(rem);
        h[i] = (uint32_t)__half_as_ushort(hb);
        l[i] = (uint32_t)__half_as_ushort(lb);
    }
    hi.x = h[0] | (h[1] << 16); hi.y = h[2] | (h[3] << 16);
    lo.x = l[0] | (l[1] << 16); lo.y = l[2] | (l[3] << 16);
}
__device__ __forceinline__ void split1(float v, bf16& h, bf16& l) {
    h = __float2bfloat16_rn(v);
    l = __float2bfloat16_rn(v - __bfloat162float(h));
}
__device__ __forceinline__ void split1h(float v, unsigned short& h, unsigned short& l) {
    __half hb = __float2half_rn(v);
    __half lb = __float2half_rn(v - __half2float(hb));
    h = __half_as_ushort(hb);
    l = __half_as_ushort(lb);
}

// ---------------- weight split: fp32 (Nvalid x K) -> bf16 planes ------------
__global__ void wsplit_kernel(const float* __restrict__ src,
                              bf16* __restrict__ hi, bf16* __restrict__ lo,
                              int Nvalid, int K, long total) {
    long i = ((long)blockIdx.x * blockDim.x + threadIdx.x) * 4;
    if (i >= total) return;
    int row = (int)(i / K);
    uint2 h, l;
    if (row < Nvalid) {
        float4 v = *(const float4*)(src + i);
        split4(v, h, l);
    } else {
        h.x = h.y = l.x = l.y = 0u;
    }
    *(uint2*)(hi + i) = h;
    *(uint2*)(lo + i) = l;
}

// ---------------- weight round: fp32 -> single fp16 plane -------------------
__global__ void wsplit_f16_kernel(const float* __restrict__ src,
                                  __half* __restrict__ hi, long total) {
    long i = ((long)blockIdx.x * blockDim.x + threadIdx.x) * 4;
    if (i >= total) return;
    float4 v = *(const float4*)(src + i);
    uint32_t h0 = (uint32_t)__half_as_ushort(__float2half_rn(v.x));
    uint32_t h1 = (uint32_t)__half_as_ushort(__float2half_rn(v.y));
    uint32_t h2 = (uint32_t)__half_as_ushort(__float2half_rn(v.z));
    uint32_t h3 = (uint32_t)__half_as_ushort(__float2half_rn(v.w));
    uint2 h; h.x = h0 | (h1 << 16); h.y = h2 | (h3 << 16);
    *(uint2*)(hi + i) = h;
}

// ---------------- x_proj split-K reduce + fused dt_r bf16 split -------------
__global__ void xp_reduce_kernel(const float* __restrict__ part,
                                 float* __restrict__ proj,
                                 bf16* __restrict__ dth, bf16* __restrict__ dtl) {
    int t = blockIdx.x * blockDim.x + threadIdx.x;   // over 4096*24
    if (t >= MTOK * 24) return;
    int row = t / 24, c4 = (t % 24) * 4;
    float4 s = *(const float4*)(part + (size_t)row * 128 + c4);
    #pragma unroll
    for (int z = 1; z < 4; ++z) {
        float4 p = *(const float4*)(part + ((size_t)z * MTOK + row) * 128 + c4);
        s.x += p.x; s.y += p.y; s.z += p.z; s.w += p.w;
    }
    *(float4*)(proj + (size_t)row * 96 + c4) = s;
    if (c4 < 64) {
        uint2 h, l;
        split4(s, h, l);
        *(uint2*)(dth + (size_t)row * 64 + c4) = h;
        *(uint2*)(dtl + (size_t)row * 64 + c4) = l;
    }
}

// ---------------- HMMA GEMM on 16-bit planes --------------------------------
// MODE 0: bf16, 3 passes, NT=4, K32, 2-stage.
// MODE 1: fp16 2-pass, NT=3, K64, 2-stage (proven round-14 geometry).
// MODE 2: fp16 1-pass, NT=2, K64, 3-stage single-barrier pipeline.
// Block tile 128x128, 2 CTAs/SM. K32 pitch 40 (80B), K64 pitch 72 (144B).
template<int ACT, bool BIAS, bool ACC, int MODE, bool K64>
__global__ __launch_bounds__(256, 2) void gemm_bf(
    int M, int N, int K,
    const bf16* __restrict__ Ah, const bf16* __restrict__ Al, int lda,
    const bf16* __restrict__ Wh, const bf16* __restrict__ Wl, int ldw,
    float* __restrict__ C, int ldc,
    const float* __restrict__ bias)
{
    constexpr int NT = (MODE == 0) ? 4 : ((MODE == 1) ? 3 : 2);
    constexpr int WT = (MODE == 2) ? 1 : 2;
    constexpr bool PIPE3 = (MODE == 2);
    constexpr int STAGES = PIPE3 ? 3 : 2;
    constexpr int PE = K64 ? 72 : 40;
    constexpr int PB = PE * 2;
    constexpr uint32_t TB = 128u * PB;
    constexpr uint32_t STAGE = NT * TB;
    constexpr int KSTEPS = K64 ? 4 : 2;
    extern __shared__ char sm[];
    int tid = threadIdx.x;
    int lane = tid & 31, wid = tid >> 5;
    int warp_m = wid >> 2, warp_n = wid & 3;
    int bm = blockIdx.x * 128, bn = blockIdx.y * 128;
    int kbase = blockIdx.z * K;
    int NC = K >> (K64 ? 6 : 5);
    uint32_t smb = smem_u32(sm);

    int a_row = warp_m * 64 + (lane & 15);
    int a_col = (lane >> 4) * 8;
    int b_row = warp_n * 32 + (lane & 7) + ((lane >> 4) << 3);
    int b_col = ((lane >> 3) & 1) * 8;

    float acc[4][4][4];
    #pragma unroll
    for (int i = 0; i < 4; ++i)
        #pragma unroll
        for (int j = 0; j < 4; ++j)
            #pragma unroll
            for (int q = 0; q < 4; ++q) acc[i][j][q] = 0.f;

    int c_row = K64 ? (tid >> 3) : (tid >> 2);
    int c_seg = K64 ? (tid & 7)  : (tid & 3);
    constexpr int LD_ITERS = K64 ? 4 : 2;
    constexpr int LD_ROWS  = K64 ? 32 : 64;
    uint32_t c_doff = (uint32_t)(c_row * PB + c_seg * 16);

    auto issue = [&](int c, int s) {
        int k0 = kbase + (c << (K64 ? 6 : 5));
        uint32_t sb = smb + (uint32_t)s * STAGE;
        #pragma unroll
        for (int it = 0; it < LD_ITERS; ++it) {
            int row = c_row + it * LD_ROWS;
            uint32_t doff = c_doff + (uint32_t)(it * LD_ROWS * PB);
            size_t aofs = (size_t)(bm + row) * lda + k0 + c_seg * 8;
            size_t wofs = (size_t)(bn + row) * ldw + k0 + c_seg * 8;
            cpasync16(sb + 0*TB + doff, Ah + aofs);
            if (MODE != 2) cpasync16(sb + 1*TB + doff, Al + aofs);
            cpasync16(sb + WT*TB + doff, Wh + wofs);
            if (MODE == 0) cpasync16(sb + 3*TB + doff, Wl + wofs);
        }
        CP_COMMIT();
    };

    int committed = (NC < 2) ? NC : 2;
    for (int c = 0; c < committed; ++c) issue(c, c % STAGES);

    for (int c = 0; c < NC; ++c) {
        if (committed > c + 1) CP_WAIT(1);
        else                   CP_WAIT(0);
        __syncthreads();
        if (PIPE3) {
            // stage (committed%3) == (c-1)%3 was freed by the barrier above
            if (committed < NC) { issue(committed, committed % 3); ++committed; }
        }

        uint32_t sb = smb + (uint32_t)(c % STAGES) * STAGE;
        #pragma unroll
        for (int ks = 0; ks < KSTEPS; ++ks) {
            uint32_t af[4][4], bh[2][4];
            #pragma unroll
            for (int i = 0; i < 4; ++i)
                ldsm4(af[i], sb + 0*TB + 2u*(uint32_t)((a_row + i*16)*PE + a_col + ks*16));
            #pragma unroll
            for (int j = 0; j < 2; ++j)
                ldsm4(bh[j], sb + WT*TB + 2u*(uint32_t)((b_row + j*16)*PE + b_col + ks*16));
            #pragma unroll
            for (int i = 0; i < 4; ++i)
                #pragma unroll
                for (int jt = 0; jt < 4; ++jt) {
                    if (MODE == 0) mma_bf  (acc[i][jt], af[i], bh[jt>>1][(jt&1)*2], bh[jt>>1][(jt&1)*2+1]);
                    else           mma_fp16(acc[i][jt], af[i], bh[jt>>1][(jt&1)*2], bh[jt>>1][(jt&1)*2+1]);
                }
            if (MODE == 0) {
                uint32_t bl[2][4];
                #pragma unroll
                for (int j = 0; j < 2; ++j)
                    ldsm4(bl[j], sb + 3*TB + 2u*(uint32_t)((b_row + j*16)*PE + b_col + ks*16));
                #pragma unroll
                for (int i = 0; i < 4; ++i)
                    #pragma unroll
                    for (int jt = 0; jt < 4; ++jt)
                        mma_bf(acc[i][jt], af[i], bl[jt>>1][(jt&1)*2], bl[jt>>1][(jt&1)*2+1]);
            }
            if (MODE != 2) {
                #pragma unroll
                for (int i = 0; i < 4; ++i)
                    ldsm4(af[i], sb + 1*TB + 2u*(uint32_t)((a_row + i*16)*PE + a_col + ks*16));
                #pragma unroll
                for (int i = 0; i < 4; ++i)
                    #pragma unroll
                    for (int jt = 0; jt < 4; ++jt) {
                        if (MODE == 0) mma_bf  (acc[i][jt], af[i], bh[jt>>1][(jt&1)*2], bh[jt>>1][(jt&1)*2+1]);
                        else           mma_fp16(acc[i][jt], af[i], bh[jt>>1][(jt&1)*2], bh[jt>>1][(jt&1)*2+1]);
                    }
            }
        }
        if (!PIPE3) {
            __syncthreads();
            if (committed < NC) { issue(committed, committed & 1); ++committed; }
        }
    }

    // epilogue
    float* Cz = C + (size_t)blockIdx.z * M * ldc;
    #pragma unroll
    for (int i = 0; i < 4; ++i) {
        int r0 = bm + warp_m * 64 + i * 16 + (lane >> 2);
        #pragma unroll
        for (int jt = 0; jt < 4; ++jt) {
            int col = bn + warp_n * 32 + jt * 8 + (lane & 3) * 2;
            #pragma unroll
            for (int half = 0; half < 2; ++half) {
                int r = r0 + half * 8;
                float vx = acc[i][jt][half * 2 + 0];
                float vy = acc[i][jt][half * 2 + 1];
                if (BIAS) { vx += bias[col]; vy += bias[col + 1]; }
                float* cp = Cz + (size_t)r * ldc + col;
                if (ACC) {
                    float2 cc = *(float2*)cp;
                    vx += cc.x; vy += cc.y;
                }
                if (ACT == 1) { vx = softplusf(vx); vy = softplusf(vy); }
                float2 o; o.x = vx; o.y = vy;
                *(float2*)cp = o;
            }
        }
    }
}

#define GSMEM_BF    (2*4*10240)   // 81920  (MODE0, K32, 2-stage)
#define GSMEM_F16P2 (2*3*18432)   // 110592 (MODE1, K64, 2-stage)
#define GSMEM_F16   (3*2*18432)   // 110592 (MODE2, K64, 3-stage)

// ---------------- embed -----------------------------------------------------
__global__ void embed_kernel(const int* __restrict__ ids,
                             const float* __restrict__ E,
                             float* __restrict__ x) {
    int i = blockIdx.x * blockDim.x + threadIdx.x;
    if (i >= MTOK * DM) return;
    int row = i >> 10;
    int d   = i & (DM - 1);
    x[i] = E[(size_t)ids[row] * DM + d];
}

// ---------------- layernorm -> 16-bit planes --------------------------------
// OUTMODE 0: bf16 hi/lo pair. 1: fp16 hi/lo pair. 2: fp16 single plane.
template<int OUTMODE>
__global__ __launch_bounds__(256) void ln_planes_kernel(
    const float* __restrict__ x,
    const float* __restrict__ w,
    const float* __restrict__ b,
    bf16* __restrict__ hi, bf16* __restrict__ lo)
{
    int row = blockIdx.x;
    int tid = threadIdx.x;
    const float4* xr = (const float4*)(x + (size_t)row * DM);
    float4 v = xr[tid];
    float s  = v.x + v.y + v.z + v.w;
    float sq = v.x*v.x + v.y*v.y + v.z*v.z + v.w*v.w;
    #pragma unroll
    for (int o = 16; o > 0; o >>= 1) {
        s  += __shfl_xor_sync(0xffffffff, s,  o);
        sq += __shfl_xor_sync(0xffffffff, sq, o);
    }
    __shared__ float rs[8], rq[8];
    int warp = tid >> 5, lane = tid & 31;
    if (lane == 0) { rs[warp] = s; rq[warp] = sq; }
    __syncthreads();
    __shared__ float smu, srstd;
    if (tid == 0) {
        float ts = 0.f, tq = 0.f;
        #pragma unroll
        for (int i = 0; i < 8; ++i) { ts += rs[i]; tq += rq[i]; }
        float mu  = ts * (1.f / DM);
        float var = tq * (1.f / DM) - mu * mu;
        smu = mu;
        srstd = rsqrtf(var + 1e-5f);
    }
    __syncthreads();
    float mu = smu, rstd = srstd;
    float4 wv = ((const float4*)w)[tid];
    float4 bv = ((const float4*)b)[tid];
    float4 o;
    o.x = (v.x - mu) * rstd * wv.x + bv.x;
    o.y = (v.y - mu) * rstd * wv.y + bv.y;
    o.z = (v.z - mu) * rstd * wv.z + bv.z;
    o.w = (v.w - mu) * rstd * wv.w + bv.w;
    if (OUTMODE == 2) {
        uint32_t h0 = (uint32_t)__half_as_ushort(__float2half_rn(o.x));
        uint32_t h1 = (uint32_t)__half_as_ushort(__float2half_rn(o.y));
        uint32_t h2 = (uint32_t)__half_as_ushort(__float2half_rn(o.z));
        uint32_t h3 = (uint32_t)__half_as_ushort(__float2half_rn(o.w));
        uint2 h; h.x = h0 | (h1 << 16); h.y = h2 | (h3 << 16);
        *(uint2*)(hi + (size_t)row * DM + tid * 4) = h;
    } else {
        uint2 h, l;
        if (OUTMODE == 1) split4h(o, h, l); else split4(o, h, l);
        *(uint2*)(hi + (size_t)row * DM + tid * 4) = h;
        *(uint2*)(lo + (size_t)row * DM + tid * 4) = l;
    }
}

// ---------------- causal dwconv (K=4) + silu -> fp32 + bf16 planes ----------
__global__ void conv_silu_kernel(const float* __restrict__ xz,
                                 const float* __restrict__ cw,
                                 const float* __restrict__ cb,
                                 float* __restrict__ xc,
                                 bf16* __restrict__ hi, bf16* __restrict__ lo) {
    int i = blockIdx.x * blockDim.x + threadIdx.x;
    if (i >= MTOK * DI_) return;
    int c  = i & (DI_ - 1);
    int bt = i >> 11;
    int t  = bt & (T_ - 1);
    float acc = cb[c];
    #pragma unroll
    for (int k = 0; k < KK; ++k) {
        int tt = t + k - (KK - 1);
        if (tt >= 0)
            acc += xz[(size_t)(bt + k - (KK - 1)) * (2*DI_) + c] * cw[c*KK + k];
    }
    float v = siluf(acc);
    xc[i] = v;
    bf16 h, l;
    split1(v, h, l);
    hi[i] = h; lo[i] = l;
}

// ---------------- selective scan with smem-staged operands, f32x2 state -----
#define CH 128
#define TT 32
#define SC_STAGEF (3*TT*CH + TT*32)      // floats per stage: 13312
#define SC_SMEM   (2*SC_STAGEF*4)        // bytes: 106496

__global__ __launch_bounds__(CH) void scan_kernel(
    const float* __restrict__ xc,
    const float* __restrict__ dtb,
    const float* __restrict__ proj,
    const float* __restrict__ xz,
    const float* __restrict__ Alog,
    const float* __restrict__ Dp,
    unsigned short* __restrict__ yh, unsigned short* __restrict__ yl)
{
    extern __shared__ float ss[];
    int tid = threadIdx.x;
    int d0  = blockIdx.x * CH;
    int b   = blockIdx.y;
    int d   = d0 + tid;

    uint32_t sbase = smem_u32(ss);

    auto issue_tile = [&](int k, int s) {
        uint32_t sb = sbase + (uint32_t)(s * SC_STAGEF * 4);
        int t0 = k * TT;
        #pragma unroll
        for (int it = 0; it < 8; ++it) {
            int j = it * CH + tid;
            int t = j >> 5;
            int off = (j & 31) * 4;
            size_t g = (size_t)(b * T_ + t0 + t);
            cpasync16(sb + 0*TT*CH*4 + j*16, xc  + g * DI_ + d0 + off);
            cpasync16(sb + 1*TT*CH*4 + j*16, dtb + g * DI_ + d0 + off);
            cpasync16(sb + 2*TT*CH*4 + j*16, xz  + g * (2*DI_) + DI_ + d0 + off);
        }
        #pragma unroll
        for (int it = 0; it < 2; ++it) {
            int j = it * CH + tid;
            int t = j >> 3;
            int c4 = (j & 7) * 4;
            size_t g = (size_t)(b * T_ + t0 + t);
            cpasync16(sb + 3*TT*CH*4 + j*16, proj + g * 96 + RR + c4);
        }
        CP_COMMIT();
    };

    float A[NS];
    bool fast = true;
    #pragma unroll
    for (int n = 0; n < NS; ++n) {
        A[n] = -expf(Alog[(size_t)d * NS + n]);
        fast = fast && (fabsf(A[n] + (float)(n + 1)) <= 1e-3f * (n + 1));
    }
    float Dv = Dp[d];
    u64 h2[8];
    #pragma unroll
    for (int j = 0; j < 8; ++j) h2[j] = 0ull;

    const int ntiles = T_ / TT;    // 64
    issue_tile(0, 0);

    for (int k = 0; k < ntiles; ++k) {
        if (k + 1 < ntiles) { issue_tile(k + 1, (k + 1) & 1); CP_WAIT(1); }
        else                { CP_WAIT(0); }
        __syncthreads();

        float* base = ss + (k & 1) * SC_STAGEF;
        float* s_u  = base;
        float* s_dt = base + 1*TT*CH;
        float* s_z  = base + 2*TT*CH;
        float* s_bc = base + 3*TT*CH;

        for (int i = 0; i < TT; ++i) {
            float u   = s_u [i*CH + tid];
            float dtv = s_dt[i*CH + tid];
            float z   = s_z [i*CH + tid];
            float du  = dtv * u;
            float accv;
            if (fast) {
                float p = __expf(-dtv);
                float q = p * p;
                u64 qq  = pack2(q, q);
                u64 dA2 = pack2(p, q);
                u64 du2 = pack2(du, du);
                u64 acc2 = 0ull;
                #pragma unroll
                for (int j = 0; j < 8; ++j) {
                    u64 B2 = *(const u64*)(s_bc + i*32 + 2*j);
                    u64 C2 = *(const u64*)(s_bc + i*32 + 16 + 2*j);
                    h2[j] = fma2_(dA2, h2[j], mul2_(du2, B2));
                    acc2  = fma2_(h2[j], C2, acc2);
                    if (j < 7) dA2 = mul2_(dA2, qq);
                }
                float a0, a1;
                unpack2(acc2, a0, a1);
                accv = a0 + a1;
            } else {
                accv = 0.f;
                #pragma unroll
                for (int j = 0; j < 8; ++j) {
                    float hx, hy;
                    unpack2(h2[j], hx, hy);
                    float dA0 = __expf(dtv * A[2*j]);
                    float dA1 = __expf(dtv * A[2*j+1]);
                    hx = dA0 * hx + du * s_bc[i*32 + 2*j];
                    hy = dA1 * hy + du * s_bc[i*32 + 2*j + 1];
                    accv += hx * s_bc[i*32 + 16 + 2*j];
                    accv += hy * s_bc[i*32 + 16 + 2*j + 1];
                    h2[j] = pack2(hx, hy);
                }
            }
            float val = (accv + u * Dv) * siluf(z);
            unsigned short vh, vl;
            split1h(val, vh, vl);
            size_t idx = (size_t)(b * T_ + k * TT + i) * DI_ + d;
            yh[idx] = vh;
            yl[idx] = vl;
        }
        __syncthreads();
    }
}

// ---------------- launch ----------------------------------------------------
extern "C" void kernel_launch(void* const* d_in, const int* in_sizes, int n_in,
                              void* d_out, int out_size) {
    const int*   ids       = (const int*)  d_in[0];
    const float* embed_W   = (const float*)d_in[1];
    const float* out_b     = (const float*)d_in[2];
    const float* ln_w      = (const float*)d_in[3];
    const float* ln_b      = (const float*)d_in[4];
    const float* norm_w    = (const float*)d_in[5];
    const float* norm_b    = (const float*)d_in[6];
    const float* in_proj_W = (const float*)d_in[7];
    const float* conv_W    = (const float*)d_in[8];
    const float* conv_b    = (const float*)d_in[9];
    const float* x_proj_W  = (const float*)d_in[10];
    const float* dt_proj_W = (const float*)d_in[11];
    const float* dt_proj_b = (const float*)d_in[12];
    const float* A_log     = (const float*)d_in[13];
    const float* D_param   = (const float*)d_in[14];
    const float* out_projW = (const float*)d_in[15];
    float* out = (float*)d_out;

    float *px, *pxz, *pxc, *pproj, *pdt, *ppart;
    bf16 *pah, *pal, *pwh, *pwl;
    cudaGetSymbolAddress((void**)&px,    g_x);
    cudaGetSymbolAddress((void**)&pxz,   g_xz);
    cudaGetSymbolAddress((void**)&pxc,   g_xc);
    cudaGetSymbolAddress((void**)&pproj, g_proj);
    cudaGetSymbolAddress((void**)&pdt,   g_dt);
    cudaGetSymbolAddress((void**)&ppart, g_part);
    cudaGetSymbolAddress((void**)&pah,   g_ah);
    cudaGetSymbolAddress((void**)&pal,   g_al);
    cudaGetSymbolAddress((void**)&pwh,   g_wh);
    cudaGetSymbolAddress((void**)&pwl,   g_wl);

    cudaFuncSetAttribute(gemm_bf<0,false,false,0,false>,
                         cudaFuncAttributeMaxDynamicSharedMemorySize, GSMEM_BF);
    cudaFuncSetAttribute(gemm_bf<1,true,false,0,false>,
                         cudaFuncAttributeMaxDynamicSharedMemorySize, GSMEM_BF);
    cudaFuncSetAttribute(gemm_bf<0,false,false,1,true>,
                         cudaFuncAttributeMaxDynamicSharedMemorySize, GSMEM_F16P2);
    cudaFuncSetAttribute(gemm_bf<0,false,true,1,true>,
                         cudaFuncAttributeMaxDynamicSharedMemorySize, GSMEM_F16P2);
    cudaFuncSetAttribute(gemm_bf<0,true,false,2,true>,
                         cudaFuncAttributeMaxDynamicSharedMemorySize, GSMEM_F16);
    cudaFuncSetAttribute(scan_kernel,
                         cudaFuncAttributeMaxDynamicSharedMemorySize, SC_SMEM);

    embed_kernel<<<(MTOK*DM + 255)/256, 256>>>(ids, embed_W, px);

    for (int l = 0; l < LL; ++l) {
        // h planes (fp16 hi/lo for MODE-1 in_proj)
        ln_planes_kernel<1><<<MTOK, 256>>>(px, norm_w + l*DM, norm_b + l*DM, pah, pal);

        // in_proj weights -> single fp16 plane, GEMM (fp16 2-pass, K64, 2-stage)
        {
            long tot = (long)2*DI_*DM;
            wsplit_f16_kernel<<<(int)((tot/4 + 255)/256), 256>>>(
                in_proj_W + (size_t)l*tot, (__half*)pwh, tot);
            gemm_bf<0,false,false,1,true><<<dim3(32, 32), 256, GSMEM_F16P2>>>(
                MTOK, 2*DI_, DM, pah, pal, DM, pwh, nullptr, DM, pxz, 2*DI_, nullptr);
        }

        // conv+silu -> xc fp32 + bf16 planes (reuse pah/pal)
        conv_silu_kernel<<<(MTOK*DI_ + 255)/256, 256>>>(
            pxz, conv_W + (size_t)l*DI_*KK, conv_b + (size_t)l*DI_, pxc, pah, pal);

        // x_proj weights (pad 96->128) bf16 planes, split-K GEMM
        {
            long tot = (long)128*DI_;
            wsplit_kernel<<<(int)((tot/4 + 255)/256), 256>>>(
                x_proj_W + (size_t)l*96*DI_, pwh, pwl, 96, DI_, tot);
            gemm_bf<0,false,false,0,false><<<dim3(32, 1, 4), 256, GSMEM_BF>>>(
                MTOK, 128, 512, pah, pal, DI_, pwh, pwl, DI_, ppart, 128, nullptr);
        }

        // dt_proj weights, fused reduce/dtr, GEMM+softplus
        {
            long tot = (long)DI_*RR;
            wsplit_kernel<<<(int)((tot/4 + 255)/256), 256>>>(
                dt_proj_W + (size_t)l*tot, pwh, pwl, DI_, RR, tot);
            xp_reduce_kernel<<<(MTOK*24 + 255)/256, 256>>>(ppart, pproj, pah, pal);
            gemm_bf<1,true,false,0,false><<<dim3(32, 16), 256, GSMEM_BF>>>(
                MTOK, DI_, RR, pah, pal, RR, pwh, pwl, RR, pdt, DI_,
                dt_proj_b + (size_t)l*DI_);
        }

        // scan -> y fp16 hi/lo planes (reuse pah/pal)
        scan_kernel<<<dim3(DI_/CH, B_), CH, SC_SMEM>>>(
            pxc, pdt, pproj, pxz,
            A_log + (size_t)l*DI_*NS, D_param + (size_t)l*DI_,
            (unsigned short*)pah, (unsigned short*)pal);

        // out_proj weights -> single fp16 plane, GEMM (fp16 2-pass, K64, 2-stage, +residual)
        {
            long tot = (long)DM*DI_;
            wsplit_f16_kernel<<<(int)((tot/4 + 255)/256), 256>>>(
                out_projW + (size_t)l*tot, (__half*)pwh, tot);
            gemm_bf<0,false,true,1,true><<<dim3(32, 8), 256, GSMEM_F16P2>>>(
                MTOK, DM, DI_, pah, pal, DI_, pwh, nullptr, DI_, px, DM, nullptr);
        }
    }

    // final LN -> single fp16 plane
    ln_planes_kernel<2><<<MTOK, 256>>>(px, ln_w, ln_b, pah, pal);

    // embed weights -> single fp16 plane, logits GEMM (1-pass fp16, K64, 3-stage)
    {
        long tot = (long)V_*DM;
        wsplit_f16_kernel<<<(int)((tot/4 + 255)/256), 256>>>(
            embed_W, (__half*)pwh, tot);
        gemm_bf<0,true,false,2,true><<<dim3(32, V_/128), 256, GSMEM_F16>>>(
            MTOK, V_, DM, pah, nullptr, DM, pwh, nullptr, DM, out, V_, out_b);
    }
}

// round 17
// speedup vs baseline: 1.0660x; 1.0054x over previous
#include <cuda_runtime.h>
#include <cuda_bf16.h>
#include <cuda_fp16.h>
#include <math.h>
#include <stdint.h>

// Problem constants
#define B_    2
#define T_    2048
#define V_    32000
#define DM    1024
#define DI_   2048
#define NS    16
#define RR    64
#define LL    4
#define KK    4
#define MTOK  (B_*T_)   // 4096

typedef __nv_bfloat16 bf16;

// ---------------- scratch (device globals; no allocation allowed) ----------
__device__ float g_x   [MTOK*DM];        // residual stream (fp32)
__device__ float g_xz  [MTOK*2*DI_];     // in_proj output
__device__ float g_xc  [MTOK*DI_];       // conv+silu output (fp32 for scan)
__device__ float g_proj[MTOK*96];        // x_proj output
__device__ float g_dt  [MTOK*DI_];       // softplus dt
__device__ float g_part[4*MTOK*128];     // split-K partials for x_proj
// 16-bit planes:
// g_wh: logits fp16 weight plane (32000x1024)
// g_wl: all layer weight planes at fixed offsets (see OFF_*)
__device__ bf16 g_ah[MTOK*DI_], g_al[MTOK*DI_];     // A planes (max 4096x2048)
__device__ bf16 g_wh[V_*DM],    g_wl[V_*DM];

// weight-plane offsets within g_wl (elements)
#define OFF_IN   0L                        // 4 x (4096*1024) fp16   = 16,777,216
#define OFF_OUT  16777216L                 // 4 x (1024*2048) fp16   =  8,388,608
#define OFF_XH   25165824L                 // 4 x (128*2048)  bf16   =  1,048,576
#define OFF_XL   26214400L
#define OFF_DTH  27262976L                 // 4 x (2048*64)   bf16   =    524,288
#define OFF_DTL  27787264L                 // ends 28,311,552 <= 32,768,000

// ---------------- helpers ---------------------------------------------------
__device__ __forceinline__ float softplusf(float x) {
    return x > 20.f ? x : log1pf(expf(x));
}
__device__ __forceinline__ float siluf(float x) {
    return x / (1.f + __expf(-x));
}
__device__ __forceinline__ uint32_t smem_u32(const void* p) {
    uint32_t a;
    asm("{ .reg .u64 t; cvta.to.shared.u64 t, %1; cvt.u32.u64 %0, t; }"
        : "=r"(a) : "l"(p));
    return a;
}
__device__ __forceinline__ void ldsm4(uint32_t* r, uint32_t addr) {
    asm volatile("ldmatrix.sync.aligned.m8n8.x4.shared.b16 {%0,%1,%2,%3}, [%4];"
        : "=r"(r[0]), "=r"(r[1]), "=r"(r[2]), "=r"(r[3]) : "r"(addr));
}
__device__ __forceinline__ void mma_bf(float* d, const uint32_t* a, uint32_t b0, uint32_t b1) {
    asm volatile(
        "mma.sync.aligned.m16n8k16.row.col.f32.bf16.bf16.f32 "
        "{%0,%1,%2,%3}, {%4,%5,%6,%7}, {%8,%9}, {%0,%1,%2,%3};"
        : "+f"(d[0]), "+f"(d[1]), "+f"(d[2]), "+f"(d[3])
        : "r"(a[0]), "r"(a[1]), "r"(a[2]), "r"(a[3]), "r"(b0), "r"(b1));
}
__device__ __forceinline__ void mma_fp16(float* d, const uint32_t* a, uint32_t b0, uint32_t b1) {
    asm volatile(
        "mma.sync.aligned.m16n8k16.row.col.f32.f16.f16.f32 "
        "{%0,%1,%2,%3}, {%4,%5,%6,%7}, {%8,%9}, {%0,%1,%2,%3};"
        : "+f"(d[0]), "+f"(d[1]), "+f"(d[2]), "+f"(d[3])
        : "r"(a[0]), "r"(a[1]), "r"(a[2]), "r"(a[3]), "r"(b0), "r"(b1));
}
__device__ __forceinline__ void cpasync16(uint32_t dst, const void* src) {
    asm volatile("cp.async.cg.shared.global [%0], [%1], 16;" :: "r"(dst), "l"(src));
}
#define CP_COMMIT() asm volatile("cp.async.commit_group;" ::: "memory")
#define CP_WAIT(n)  asm volatile("cp.async.wait_group %0;" :: "n"(n) : "memory")

// packed f32x2 helpers (sm_100+ baseline PTX)
typedef unsigned long long u64;
__device__ __forceinline__ u64 pack2(float x, float y) {
    u64 r; asm("mov.b64 %0, {%1, %2};" : "=l"(r) : "f"(x), "f"(y)); return r;
}
__device__ __forceinline__ void unpack2(u64 v, float& x, float& y) {
    asm("mov.b64 {%0, %1}, %2;" : "=f"(x), "=f"(y) : "l"(v));
}
__device__ __forceinline__ u64 mul2_(u64 a, u64 b) {
    u64 r; asm("mul.rn.f32x2 %0, %1, %2;" : "=l"(r) : "l"(a), "l"(b)); return r;
}
__device__ __forceinline__ u64 fma2_(u64 a, u64 b, u64 c) {
    u64 r; asm("fma.rn.f32x2 %0, %1, %2, %3;" : "=l"(r) : "l"(a), "l"(b), "l"(c)); return r;
}

// hi/lo bf16 split of 4 floats
__device__ __forceinline__ void split4(float4 v, uint2& hi, uint2& lo) {
    float f[4] = {v.x, v.y, v.z, v.w};
    uint32_t h[4], l[4];
    #pragma unroll
    for (int i = 0; i < 4; ++i) {
        bf16 hb = __float2bfloat16_rn(f[i]);
        float rem = f[i] - __bfloat162float(hb);
        bf16 lb = __float2bfloat16_rn(rem);
        h[i] = (uint32_t)__bfloat16_as_ushort(hb);
        l[i] = (uint32_t)__bfloat16_as_ushort(lb);
    }
    hi.x = h[0] | (h[1] << 16); hi.y = h[2] | (h[3] << 16);
    lo.x = l[0] | (l[1] << 16); lo.y = l[2] | (l[3] << 16);
}
// hi/lo fp16 split of 4 floats
__device__ __forceinline__ void split4h(float4 v, uint2& hi, uint2& lo) {
    float f[4] = {v.x, v.y, v.z, v.w};
    uint32_t h[4], l[4];
    #pragma unroll
    for (int i = 0; i < 4; ++i) {
        __half hb = __float2half_rn(f[i]);
        float rem = f[i] - __half2float(hb);
        __half lb = __float2half_rn(rem);
        h[i] = (uint32_t)__half_as_ushort(hb);
        l[i] = (uint32_t)__half_as_ushort(lb);
    }
    hi.x = h[0] | (h[1] << 16); hi.y = h[2] | (h[3] << 16);
    lo.x = l[0] | (l[1] << 16); lo.y = l[2] | (l[3] << 16);
}
__device__ __forceinline__ void split1(float v, bf16& h, bf16& l) {
    h = __float2bfloat16_rn(v);
    l = __float2bfloat16_rn(v - __bfloat162float(h));
}
__device__ __forceinline__ void split1h(float v, unsigned short& h, unsigned short& l) {
    __half hb = __float2half_rn(v);
    __half lb = __float2half_rn(v - __half2float(hb));
    h = __half_as_ushort(hb);
    l = __half_as_ushort(lb);
}

// ---------------- weight split: fp32 -> bf16 planes (all rows valid) --------
__global__ void wsplit_kernel(const float* __restrict__ src,
                              bf16* __restrict__ hi, bf16* __restrict__ lo,
                              long total) {
    long i = ((long)blockIdx.x * blockDim.x + threadIdx.x) * 4;
    if (i >= total) return;
    float4 v = *(const float4*)(src + i);
    uint2 h, l;
    split4(v, h, l);
    *(uint2*)(hi + i) = h;
    *(uint2*)(lo + i) = l;
}

// ---------------- x_proj split (all layers): (L,96,DI) -> padded (L,128,DI) -
__global__ void wsplit_xp_kernel(const float* __restrict__ src,
                                 bf16* __restrict__ hi, bf16* __restrict__ lo) {
    long i = ((long)blockIdx.x * blockDim.x + threadIdx.x) * 4;   // over L*128*DI
    if (i >= (long)LL * 128 * DI_) return;
    int l   = (int)(i / (128L * DI_));
    long rem = i - (long)l * 128 * DI_;
    int row = (int)(rem / DI_);
    long col = rem - (long)row * DI_;
    uint2 h, lw;
    if (row < 96) {
        float4 v = *(const float4*)(src + ((size_t)l * 96 + row) * DI_ + col);
        split4(v, h, lw);
    } else {
        h.x = h.y = lw.x = lw.y = 0u;
    }
    *(uint2*)(hi + i) = h;
    *(uint2*)(lo + i) = lw;
}

// ---------------- weight round: fp32 -> single fp16 plane -------------------
__global__ void wsplit_f16_kernel(const float* __restrict__ src,
                                  __half* __restrict__ hi, long total) {
    long i = ((long)blockIdx.x * blockDim.x + threadIdx.x) * 4;
    if (i >= total) return;
    float4 v = *(const float4*)(src + i);
    uint32_t h0 = (uint32_t)__half_as_ushort(__float2half_rn(v.x));
    uint32_t h1 = (uint32_t)__half_as_ushort(__float2half_rn(v.y));
    uint32_t h2 = (uint32_t)__half_as_ushort(__float2half_rn(v.z));
    uint32_t h3 = (uint32_t)__half_as_ushort(__float2half_rn(v.w));
    uint2 h; h.x = h0 | (h1 << 16); h.y = h2 | (h3 << 16);
    *(uint2*)(hi + i) = h;
}

// ---------------- x_proj split-K reduce + fused dt_r bf16 split -------------
__global__ void xp_reduce_kernel(const float* __restrict__ part,
                                 float* __restrict__ proj,
                                 bf16* __restrict__ dth, bf16* __restrict__ dtl) {
    int t = blockIdx.x * blockDim.x + threadIdx.x;   // over 4096*24
    if (t >= MTOK * 24) return;
    int row = t / 24, c4 = (t % 24) * 4;
    float4 s = *(const float4*)(part + (size_t)row * 128 + c4);
    #pragma unroll
    for (int z = 1; z < 4; ++z) {
        float4 p = *(const float4*)(part + ((size_t)z * MTOK + row) * 128 + c4);
        s.x += p.x; s.y += p.y; s.z += p.z; s.w += p.w;
    }
    *(float4*)(proj + (size_t)row * 96 + c4) = s;
    if (c4 < 64) {
        uint2 h, l;
        split4(s, h, l);
        *(uint2*)(dth + (size_t)row * 64 + c4) = h;
        *(uint2*)(dtl + (size_t)row * 64 + c4) = l;
    }
}

// ---------------- HMMA GEMM on 16-bit planes --------------------------------
// MODE 0: bf16, 3 passes, NT=4, K32, 2-stage.
// MODE 1: fp16 2-pass, NT=3, K64, 2-stage.
// MODE 2: fp16 1-pass, NT=2, K64, 3-stage single-barrier pipeline.
template<int ACT, bool BIAS, bool ACC, int MODE, bool K64>
__global__ __launch_bounds__(256, 2) void gemm_bf(
    int M, int N, int K,
    const bf16* __restrict__ Ah, const bf16* __restrict__ Al, int lda,
    const bf16* __restrict__ Wh, const bf16* __restrict__ Wl, int ldw,
    float* __restrict__ C, int ldc,
    const float* __restrict__ bias)
{
    constexpr int NT = (MODE == 0) ? 4 : ((MODE == 1) ? 3 : 2);
    constexpr int WT = (MODE == 2) ? 1 : 2;
    constexpr bool PIPE3 = (MODE == 2);
    constexpr int STAGES = PIPE3 ? 3 : 2;
    constexpr int PE = K64 ? 72 : 40;
    constexpr int PB = PE * 2;
    constexpr uint32_t TB = 128u * PB;
    constexpr uint32_t STAGE = NT * TB;
    constexpr int KSTEPS = K64 ? 4 : 2;
    extern __shared__ char sm[];
    int tid = threadIdx.x;
    int lane = tid & 31, wid = tid >> 5;
    int warp_m = wid >> 2, warp_n = wid & 3;
    int bm = blockIdx.x * 128, bn = blockIdx.y * 128;
    int kbase = blockIdx.z * K;
    int NC = K >> (K64 ? 6 : 5);
    uint32_t smb = smem_u32(sm);

    int a_row = warp_m * 64 + (lane & 15);
    int a_col = (lane >> 4) * 8;
    int b_row = warp_n * 32 + (lane & 7) + ((lane >> 4) << 3);
    int b_col = ((lane >> 3) & 1) * 8;

    float acc[4][4][4];
    #pragma unroll
    for (int i = 0; i < 4; ++i)
        #pragma unroll
        for (int j = 0; j < 4; ++j)
            #pragma unroll
            for (int q = 0; q < 4; ++q) acc[i][j][q] = 0.f;

    int c_row = K64 ? (tid >> 3) : (tid >> 2);
    int c_seg = K64 ? (tid & 7)  : (tid & 3);
    constexpr int LD_ITERS = K64 ? 4 : 2;
    constexpr int LD_ROWS  = K64 ? 32 : 64;
    uint32_t c_doff = (uint32_t)(c_row * PB + c_seg * 16);

    auto issue = [&](int c, int s) {
        int k0 = kbase + (c << (K64 ? 6 : 5));
        uint32_t sb = smb + (uint32_t)s * STAGE;
        #pragma unroll
        for (int it = 0; it < LD_ITERS; ++it) {
            int row = c_row + it * LD_ROWS;
            uint32_t doff = c_doff + (uint32_t)(it * LD_ROWS * PB);
            size_t aofs = (size_t)(bm + row) * lda + k0 + c_seg * 8;
            size_t wofs = (size_t)(bn + row) * ldw + k0 + c_seg * 8;
            cpasync16(sb + 0*TB + doff, Ah + aofs);
            if (MODE != 2) cpasync16(sb + 1*TB + doff, Al + aofs);
            cpasync16(sb + WT*TB + doff, Wh + wofs);
            if (MODE == 0) cpasync16(sb + 3*TB + doff, Wl + wofs);
        }
        CP_COMMIT();
    };

    int committed = (NC < 2) ? NC : 2;
    for (int c = 0; c < committed; ++c) issue(c, c % STAGES);

    for (int c = 0; c < NC; ++c) {
        if (committed > c + 1) CP_WAIT(1);
        else                   CP_WAIT(0);
        __syncthreads();
        if (PIPE3) {
            if (committed < NC) { issue(committed, committed % 3); ++committed; }
        }

        uint32_t sb = smb + (uint32_t)(c % STAGES) * STAGE;
        #pragma unroll
        for (int ks = 0; ks < KSTEPS; ++ks) {
            uint32_t af[4][4], bh[2][4];
            #pragma unroll
            for (int i = 0; i < 4; ++i)
                ldsm4(af[i], sb + 0*TB + 2u*(uint32_t)((a_row + i*16)*PE + a_col + ks*16));
            #pragma unroll
            for (int j = 0; j < 2; ++j)
                ldsm4(bh[j], sb + WT*TB + 2u*(uint32_t)((b_row + j*16)*PE + b_col + ks*16));
            #pragma unroll
            for (int i = 0; i < 4; ++i)
                #pragma unroll
                for (int jt = 0; jt < 4; ++jt) {
                    if (MODE == 0) mma_bf  (acc[i][jt], af[i], bh[jt>>1][(jt&1)*2], bh[jt>>1][(jt&1)*2+1]);
                    else           mma_fp16(acc[i][jt], af[i], bh[jt>>1][(jt&1)*2], bh[jt>>1][(jt&1)*2+1]);
                }
            if (MODE == 0) {
                uint32_t bl[2][4];
                #pragma unroll
                for (int j = 0; j < 2; ++j)
                    ldsm4(bl[j], sb + 3*TB + 2u*(uint32_t)((b_row + j*16)*PE + b_col + ks*16));
                #pragma unroll
                for (int i = 0; i < 4; ++i)
                    #pragma unroll
                    for (int jt = 0; jt < 4; ++jt)
                        mma_bf(acc[i][jt], af[i], bl[jt>>1][(jt&1)*2], bl[jt>>1][(jt&1)*2+1]);
            }
            if (MODE != 2) {
                #pragma unroll
                for (int i = 0; i < 4; ++i)
                    ldsm4(af[i], sb + 1*TB + 2u*(uint32_t)((a_row + i*16)*PE + a_col + ks*16));
                #pragma unroll
                for (int i = 0; i < 4; ++i)
                    #pragma unroll
                    for (int jt = 0; jt < 4; ++jt) {
                        if (MODE == 0) mma_bf  (acc[i][jt], af[i], bh[jt>>1][(jt&1)*2], bh[jt>>1][(jt&1)*2+1]);
                        else           mma_fp16(acc[i][jt], af[i], bh[jt>>1][(jt&1)*2], bh[jt>>1][(jt&1)*2+1]);
                    }
            }
        }
        if (!PIPE3) {
            __syncthreads();
            if (committed < NC) { issue(committed, committed & 1); ++committed; }
        }
    }

    // epilogue
    float* Cz = C + (size_t)blockIdx.z * M * ldc;
    #pragma unroll
    for (int i = 0; i < 4; ++i) {
        int r0 = bm + warp_m * 64 + i * 16 + (lane >> 2);
        #pragma unroll
        for (int jt = 0; jt < 4; ++jt) {
            int col = bn + warp_n * 32 + jt * 8 + (lane & 3) * 2;
            #pragma unroll
            for (int half = 0; half < 2; ++half) {
                int r = r0 + half * 8;
                float vx = acc[i][jt][half * 2 + 0];
                float vy = acc[i][jt][half * 2 + 1];
                if (BIAS) { vx += bias[col]; vy += bias[col + 1]; }
                float* cp = Cz + (size_t)r * ldc + col;
                if (ACC) {
                    float2 cc = *(float2*)cp;
                    vx += cc.x; vy += cc.y;
                }
                if (ACT == 1) { vx = softplusf(vx); vy = softplusf(vy); }
                float2 o; o.x = vx; o.y = vy;
                *(float2*)cp = o;
            }
        }
    }
}

#define GSMEM_BF    (2*4*10240)   // 81920  (MODE0, K32, 2-stage)
#define GSMEM_F16P2 (2*3*18432)   // 110592 (MODE1, K64, 2-stage)
#define GSMEM_F16   (3*2*18432)   // 110592 (MODE2, K64, 3-stage)

// ---------------- embed -----------------------------------------------------
__global__ void embed_kernel(const int* __restrict__ ids,
                             const float* __restrict__ E,
                             float* __restrict__ x) {
    int i = blockIdx.x * blockDim.x + threadIdx.x;
    if (i >= MTOK * DM) return;
    int row = i >> 10;
    int d   = i & (DM - 1);
    x[i] = E[(size_t)ids[row] * DM + d];
}

// ---------------- layernorm -> 16-bit planes --------------------------------
// OUTMODE 1: fp16 hi/lo pair. 2: fp16 single plane.
template<int OUTMODE>
__global__ __launch_bounds__(256) void ln_planes_kernel(
    const float* __restrict__ x,
    const float* __restrict__ w,
    const float* __restrict__ b,
    bf16* __restrict__ hi, bf16* __restrict__ lo)
{
    int row = blockIdx.x;
    int tid = threadIdx.x;
    const float4* xr = (const float4*)(x + (size_t)row * DM);
    float4 v = xr[tid];
    float s  = v.x + v.y + v.z + v.w;
    float sq = v.x*v.x + v.y*v.y + v.z*v.z + v.w*v.w;
    #pragma unroll
    for (int o = 16; o > 0; o >>= 1) {
        s  += __shfl_xor_sync(0xffffffff, s,  o);
        sq += __shfl_xor_sync(0xffffffff, sq, o);
    }
    __shared__ float rs[8], rq[8];
    int warp = tid >> 5, lane = tid & 31;
    if (lane == 0) { rs[warp] = s; rq[warp] = sq; }
    __syncthreads();
    __shared__ float smu, srstd;
    if (tid == 0) {
        float ts = 0.f, tq = 0.f;
        #pragma unroll
        for (int i = 0; i < 8; ++i) { ts += rs[i]; tq += rq[i]; }
        float mu  = ts * (1.f / DM);
        float var = tq * (1.f / DM) - mu * mu;
        smu = mu;
        srstd = rsqrtf(var + 1e-5f);
    }
    __syncthreads();
    float mu = smu, rstd = srstd;
    float4 wv = ((const float4*)w)[tid];
    float4 bv = ((const float4*)b)[tid];
    float4 o;
    o.x = (v.x - mu) * rstd * wv.x + bv.x;
    o.y = (v.y - mu) * rstd * wv.y + bv.y;
    o.z = (v.z - mu) * rstd * wv.z + bv.z;
    o.w = (v.w - mu) * rstd * wv.w + bv.w;
    if (OUTMODE == 2) {
        uint32_t h0 = (uint32_t)__half_as_ushort(__float2half_rn(o.x));
        uint32_t h1 = (uint32_t)__half_as_ushort(__float2half_rn(o.y));
        uint32_t h2 = (uint32_t)__half_as_ushort(__float2half_rn(o.z));
        uint32_t h3 = (uint32_t)__half_as_ushort(__float2half_rn(o.w));
        uint2 h; h.x = h0 | (h1 << 16); h.y = h2 | (h3 << 16);
        *(uint2*)(hi + (size_t)row * DM + tid * 4) = h;
    } else {
        uint2 h, l;
        split4h(o, h, l);
        *(uint2*)(hi + (size_t)row * DM + tid * 4) = h;
        *(uint2*)(lo + (size_t)row * DM + tid * 4) = l;
    }
}

// ---------------- causal dwconv (K=4) + silu -> fp32 + bf16 planes ----------
__global__ void conv_silu_kernel(const float* __restrict__ xz,
                                 const float* __restrict__ cw,
                                 const float* __restrict__ cb,
                                 float* __restrict__ xc,
                                 bf16* __restrict__ hi, bf16* __restrict__ lo) {
    int i = blockIdx.x * blockDim.x + threadIdx.x;
    if (i >= MTOK * DI_) return;
    int c  = i & (DI_ - 1);
    int bt = i >> 11;
    int t  = bt & (T_ - 1);
    float acc = cb[c];
    #pragma unroll
    for (int k = 0; k < KK; ++k) {
        int tt = t + k - (KK - 1);
        if (tt >= 0)
            acc += xz[(size_t)(bt + k - (KK - 1)) * (2*DI_) + c] * cw[c*KK + k];
    }
    float v = siluf(acc);
    xc[i] = v;
    bf16 h, l;
    split1(v, h, l);
    hi[i] = h; lo[i] = l;
}

// ---------------- selective scan with smem-staged operands, f32x2 state -----
#define CH 128
#define TT 32
#define SC_STAGEF (3*TT*CH + TT*32)      // floats per stage: 13312
#define SC_SMEM   (2*SC_STAGEF*4)        // bytes: 106496

__global__ __launch_bounds__(CH) void scan_kernel(
    const float* __restrict__ xc,
    const float* __restrict__ dtb,
    const float* __restrict__ proj,
    const float* __restrict__ xz,
    const float* __restrict__ Alog,
    const float* __restrict__ Dp,
    unsigned short* __restrict__ yh, unsigned short* __restrict__ yl)
{
    extern __shared__ float ss[];
    int tid = threadIdx.x;
    int d0  = blockIdx.x * CH;
    int b   = blockIdx.y;
    int d   = d0 + tid;

    uint32_t sbase = smem_u32(ss);

    auto issue_tile = [&](int k, int s) {
        uint32_t sb = sbase + (uint32_t)(s * SC_STAGEF * 4);
        int t0 = k * TT;
        #pragma unroll
        for (int it = 0; it < 8; ++it) {
            int j = it * CH + tid;
            int t = j >> 5;
            int off = (j & 31) * 4;
            size_t g = (size_t)(b * T_ + t0 + t);
            cpasync16(sb + 0*TT*CH*4 + j*16, xc  + g * DI_ + d0 + off);
            cpasync16(sb + 1*TT*CH*4 + j*16, dtb + g * DI_ + d0 + off);
            cpasync16(sb + 2*TT*CH*4 + j*16, xz  + g * (2*DI_) + DI_ + d0 + off);
        }
        #pragma unroll
        for (int it = 0; it < 2; ++it) {
            int j = it * CH + tid;
            int t = j >> 3;
            int c4 = (j & 7) * 4;
            size_t g = (size_t)(b * T_ + t0 + t);
            cpasync16(sb + 3*TT*CH*4 + j*16, proj + g * 96 + RR + c4);
        }
        CP_COMMIT();
    };

    float A[NS];
    bool fast = true;
    #pragma unroll
    for (int n = 0; n < NS; ++n) {
        A[n] = -expf(Alog[(size_t)d * NS + n]);
        fast = fast && (fabsf(A[n] + (float)(n + 1)) <= 1e-3f * (n + 1));
    }
    float Dv = Dp[d];
    u64 h2[8];
    #pragma unroll
    for (int j = 0; j < 8; ++j) h2[j] = 0ull;

    const int ntiles = T_ / TT;    // 64
    issue_tile(0, 0);

    for (int k = 0; k < ntiles; ++k) {
        if (k + 1 < ntiles) { issue_tile(k + 1, (k + 1) & 1); CP_WAIT(1); }
        else                { CP_WAIT(0); }
        __syncthreads();

        float* base = ss + (k & 1) * SC_STAGEF;
        float* s_u  = base;
        float* s_dt = base + 1*TT*CH;
        float* s_z  = base + 2*TT*CH;
        float* s_bc = base + 3*TT*CH;

        for (int i = 0; i < TT; ++i) {
            float u   = s_u [i*CH + tid];
            float dtv = s_dt[i*CH + tid];
            float z   = s_z [i*CH + tid];
            float du  = dtv * u;
            float accv;
            if (fast) {
                float p = __expf(-dtv);
                float q = p * p;
                u64 qq  = pack2(q, q);
                u64 dA2 = pack2(p, q);
                u64 du2 = pack2(du, du);
                u64 acc2 = 0ull;
                #pragma unroll
                for (int j = 0; j < 8; ++j) {
                    u64 B2 = *(const u64*)(s_bc + i*32 + 2*j);
                    u64 C2 = *(const u64*)(s_bc + i*32 + 16 + 2*j);
                    h2[j] = fma2_(dA2, h2[j], mul2_(du2, B2));
                    acc2  = fma2_(h2[j], C2, acc2);
                    if (j < 7) dA2 = mul2_(dA2, qq);
                }
                float a0, a1;
                unpack2(acc2, a0, a1);
                accv = a0 + a1;
            } else {
                accv = 0.f;
                #pragma unroll
                for (int j = 0; j < 8; ++j) {
                    float hx, hy;
                    unpack2(h2[j], hx, hy);
                    float dA0 = __expf(dtv * A[2*j]);
                    float dA1 = __expf(dtv * A[2*j+1]);
                    hx = dA0 * hx + du * s_bc[i*32 + 2*j];
                    hy = dA1 * hy + du * s_bc[i*32 + 2*j + 1];
                    accv += hx * s_bc[i*32 + 16 + 2*j];
                    accv += hy * s_bc[i*32 + 16 + 2*j + 1];
                    h2[j] = pack2(hx, hy);
                }
            }
            float val = (accv + u * Dv) * siluf(z);
            unsigned short vh, vl;
            split1h(val, vh, vl);
            size_t idx = (size_t)(b * T_ + k * TT + i) * DI_ + d;
            yh[idx] = vh;
            yl[idx] = vl;
        }
        __syncthreads();
    }
}

// ---------------- launch ----------------------------------------------------
extern "C" void kernel_launch(void* const* d_in, const int* in_sizes, int n_in,
                              void* d_out, int out_size) {
    const int*   ids       = (const int*)  d_in[0];
    const float* embed_W   = (const float*)d_in[1];
    const float* out_b     = (const float*)d_in[2];
    const float* ln_w      = (const float*)d_in[3];
    const float* ln_b      = (const float*)d_in[4];
    const float* norm_w    = (const float*)d_in[5];
    const float* norm_b    = (const float*)d_in[6];
    const float* in_proj_W = (const float*)d_in[7];
    const float* conv_W    = (const float*)d_in[8];
    const float* conv_b    = (const float*)d_in[9];
    const float* x_proj_W  = (const float*)d_in[10];
    const float* dt_proj_W = (const float*)d_in[11];
    const float* dt_proj_b = (const float*)d_in[12];
    const float* A_log     = (const float*)d_in[13];
    const float* D_param   = (const float*)d_in[14];
    const float* out_projW = (const float*)d_in[15];
    float* out = (float*)d_out;

    float *px, *pxz, *pxc, *pproj, *pdt, *ppart;
    bf16 *pah, *pal, *pwh, *pwl;
    cudaGetSymbolAddress((void**)&px,    g_x);
    cudaGetSymbolAddress((void**)&pxz,   g_xz);
    cudaGetSymbolAddress((void**)&pxc,   g_xc);
    cudaGetSymbolAddress((void**)&pproj, g_proj);
    cudaGetSymbolAddress((void**)&pdt,   g_dt);
    cudaGetSymbolAddress((void**)&ppart, g_part);
    cudaGetSymbolAddress((void**)&pah,   g_ah);
    cudaGetSymbolAddress((void**)&pal,   g_al);
    cudaGetSymbolAddress((void**)&pwh,   g_wh);
    cudaGetSymbolAddress((void**)&pwl,   g_wl);

    cudaFuncSetAttribute(gemm_bf<0,false,false,0,false>,
                         cudaFuncAttributeMaxDynamicSharedMemorySize, GSMEM_BF);
    cudaFuncSetAttribute(gemm_bf<1,true,false,0,false>,
                         cudaFuncAttributeMaxDynamicSharedMemorySize, GSMEM_BF);
    cudaFuncSetAttribute(gemm_bf<0,false,false,1,true>,
                         cudaFuncAttributeMaxDynamicSharedMemorySize, GSMEM_F16P2);
    cudaFuncSetAttribute(gemm_bf<0,false,true,1,true>,
                         cudaFuncAttributeMaxDynamicSharedMemorySize, GSMEM_F16P2);
    cudaFuncSetAttribute(gemm_bf<0,true,false,2,true>,
                         cudaFuncAttributeMaxDynamicSharedMemorySize, GSMEM_F16);
    cudaFuncSetAttribute(scan_kernel,
                         cudaFuncAttributeMaxDynamicSharedMemorySize, SC_SMEM);

    // ---- batched weight splits for ALL layers + logits (5 launches) ----
    {
        long tot_in  = (long)LL * 2 * DI_ * DM;   // 16,777,216
        wsplit_f16_kernel<<<(int)((tot_in/4 + 255)/256), 256>>>(
            in_proj_W, (__half*)(pwl + OFF_IN), tot_in);
        long tot_out = (long)LL * DM * DI_;       // 8,388,608
        wsplit_f16_kernel<<<(int)((tot_out/4 + 255)/256), 256>>>(
            out_projW, (__half*)(pwl + OFF_OUT), tot_out);
        long tot_xp  = (long)LL * 128 * DI_;      // 1,048,576 (padded)
        wsplit_xp_kernel<<<(int)((tot_xp/4 + 255)/256), 256>>>(
            x_proj_W, pwl + OFF_XH, pwl + OFF_XL);
        long tot_dt  = (long)LL * DI_ * RR;       // 524,288
        wsplit_kernel<<<(int)((tot_dt/4 + 255)/256), 256>>>(
            dt_proj_W, pwl + OFF_DTH, pwl + OFF_DTL, tot_dt);
        long tot_lg  = (long)V_ * DM;
        wsplit_f16_kernel<<<(int)((tot_lg/4 + 255)/256), 256>>>(
            embed_W, (__half*)pwh, tot_lg);
    }

    embed_kernel<<<(MTOK*DM + 255)/256, 256>>>(ids, embed_W, px);

    for (int l = 0; l < LL; ++l) {
        // h planes (fp16 hi/lo for MODE-1 in_proj)
        ln_planes_kernel<1><<<MTOK, 256>>>(px, norm_w + l*DM, norm_b + l*DM, pah, pal);

        // in_proj GEMM (fp16 2-pass, K64, 2-stage)
        gemm_bf<0,false,false,1,true><<<dim3(32, 32), 256, GSMEM_F16P2>>>(
            MTOK, 2*DI_, DM, pah, pal, DM,
            pwl + OFF_IN + (long)l * 2*DI_*DM, nullptr, DM, pxz, 2*DI_, nullptr);

        // conv+silu -> xc fp32 + bf16 planes (reuse pah/pal)
        conv_silu_kernel<<<(MTOK*DI_ + 255)/256, 256>>>(
            pxz, conv_W + (size_t)l*DI_*KK, conv_b + (size_t)l*DI_, pxc, pah, pal);

        // x_proj split-K GEMM (bf16 3-pass)
        gemm_bf<0,false,false,0,false><<<dim3(32, 1, 4), 256, GSMEM_BF>>>(
            MTOK, 128, 512, pah, pal, DI_,
            pwl + OFF_XH + (long)l * 128*DI_, pwl + OFF_XL + (long)l * 128*DI_, DI_,
            ppart, 128, nullptr);

        // fused reduce/dtr split, then dt GEMM+softplus (bf16 3-pass)
        xp_reduce_kernel<<<(MTOK*24 + 255)/256, 256>>>(ppart, pproj, pah, pal);
        gemm_bf<1,true,false,0,false><<<dim3(32, 16), 256, GSMEM_BF>>>(
            MTOK, DI_, RR, pah, pal, RR,
            pwl + OFF_DTH + (long)l * DI_*RR, pwl + OFF_DTL + (long)l * DI_*RR, RR,
            pdt, DI_, dt_proj_b + (size_t)l*DI_);

        // scan -> y fp16 hi/lo planes (reuse pah/pal)
        scan_kernel<<<dim3(DI_/CH, B_), CH, SC_SMEM>>>(
            pxc, pdt, pproj, pxz,
            A_log + (size_t)l*DI_*NS, D_param + (size_t)l*DI_,
            (unsigned short*)pah, (unsigned short*)pal);

        // out_proj GEMM (fp16 2-pass, K64, 2-stage, +residual)
        gemm_bf<0,false,true,1,true><<<dim3(32, 8), 256, GSMEM_F16P2>>>(
            MTOK, DM, DI_, pah, pal, DI_,
            pwl + OFF_OUT + (long)l * DM*DI_, nullptr, DI_, px, DM, nullptr);
    }

    // final LN -> single fp16 plane
    ln_planes_kernel<2><<<MTOK, 256>>>(px, ln_w, ln_b, pah, pal);

    // logits GEMM (1-pass fp16, K64, 3-stage)
    gemm_bf<0,true,false,2,true><<<dim3(32, V_/128), 256, GSMEM_F16>>>(
        MTOK, V_, DM, pah, nullptr, DM, pwh, nullptr, DM, out, V_, out_b);
}